// round 4
// baseline (speedup 1.0000x reference)
#include <cuda_runtime.h>
#include <cstdint>

#define N_NODES 50000
#define N_EDGES 800000
#define DIM 64
#define HID 128
#define DT 0.1f
#define TAU 2.0f
#define LAMBDA_W 1e-4f
#define N_STEPS 10

// ---------------- scratch (device globals; no allocations allowed) ----------------
__device__ float g_x[N_NODES * DIM];
__device__ float g_e[N_NODES * DIM];
__device__ float g_msg[N_NODES * DIM];
__device__ int2  g_edge[N_EDGES];       // original-order (src,tgt)
__device__ int   g_cnt[N_NODES];        // in-degree histogram
__device__ int   g_fill[N_NODES];       // scatter fill counters
__device__ int   g_rowstart[N_NODES + 1];
__device__ int   g_srcs[N_EDGES];       // CSR: src per sorted edge
__device__ float g_ws[N_EDGES];         // CSR: weight per sorted edge
__device__ int   g_perm[N_EDGES];       // sorted pos -> original edge id
__device__ int   g_is64;

// ---------------- dtype detection for edge_index (int32 vs int64) -----------------
__global__ void detect_kernel(const int* __restrict__ ei32) {
    int v = ei32[2 * threadIdx.x + 1];
    unsigned nz = __ballot_sync(0xffffffffu, v != 0);
    if (threadIdx.x == 0) g_is64 = (nz == 0u) ? 1 : 0;
}

__global__ void zero_kernel() {
    int i = blockIdx.x * blockDim.x + threadIdx.x;
    if (i < N_NODES) { g_cnt[i] = 0; g_fill[i] = 0; }
}

// convert + histogram
__global__ void convert_kernel(const void* __restrict__ ei) {
    int i = blockIdx.x * blockDim.x + threadIdx.x;
    if (i >= N_EDGES) return;
    int s, t;
    if (g_is64) {
        const long long* p = (const long long*)ei;
        s = (int)p[i];
        t = (int)p[N_EDGES + i];
    } else {
        const int* p = (const int*)ei;
        s = p[i];
        t = p[N_EDGES + i];
    }
    g_edge[i] = make_int2(s, t);
    atomicAdd(&g_cnt[t], 1);
}

// single-block exclusive scan of g_cnt -> g_rowstart
__global__ void __launch_bounds__(1024) scan_kernel() {
    __shared__ int sums[1024];
    const int CH = (N_NODES + 1023) / 1024;  // 49
    int tid = threadIdx.x;
    int start = tid * CH;
    int local = 0;
    for (int i = 0; i < CH; i++) {
        int idx = start + i;
        if (idx < N_NODES) local += g_cnt[idx];
    }
    sums[tid] = local;
    __syncthreads();
    for (int off = 1; off < 1024; off <<= 1) {
        int v = (tid >= off) ? sums[tid - off] : 0;
        __syncthreads();
        sums[tid] += v;
        __syncthreads();
    }
    int prefix = (tid > 0) ? sums[tid - 1] : 0;
    for (int i = 0; i < CH; i++) {
        int idx = start + i;
        if (idx < N_NODES) {
            g_rowstart[idx] = prefix;
            prefix += g_cnt[idx];
        }
    }
    if (tid == 0) g_rowstart[N_NODES] = N_EDGES;
}

__global__ void scatter_kernel(const float* __restrict__ w_in) {
    int i = blockIdx.x * blockDim.x + threadIdx.x;
    if (i >= N_EDGES) return;
    int2 st = g_edge[i];
    int pos = g_rowstart[st.y] + atomicAdd(&g_fill[st.y], 1);
    g_srcs[pos] = st.x;
    g_ws[pos]   = w_in[i];
    g_perm[pos] = i;
}

__global__ void init_nodes_kernel(const float* __restrict__ x_in) {
    int i = blockIdx.x * blockDim.x + threadIdx.x;
    if (i < N_NODES * DIM) {
        g_x[i] = x_in[i];
        g_e[i] = 0.0f;
    }
}

// ---------------- fused CSR edge kernel: plasticity (step t) + messages (t+1) -----
// One warp per tgt node; lane owns 2 dims (float2). No atomics.
template <bool PLAST, bool MSG>
__global__ void __launch_bounds__(256) edge_csr_kernel(const float* __restrict__ etap,
                                                       const float* __restrict__ etam) {
    int node = blockIdx.x * 8 + (threadIdx.x >> 5);
    if (node >= N_NODES) return;
    int lane = threadIdx.x & 31;

    const float2* __restrict__ x2 = (const float2*)g_x;
    const float2* __restrict__ e2 = (const float2*)g_e;

    int beg = g_rowstart[node];
    int end = g_rowstart[node + 1];

    float2 xt = make_float2(0.f, 0.f), et = make_float2(0.f, 0.f);
    float ep = 0.f, em = 0.f;
    if (PLAST) {
        xt = x2[node * 32 + lane];
        et = e2[node * 32 + lane];
        ep = __ldg(etap);
        em = __ldg(etam);
    }

    float2 macc = make_float2(0.f, 0.f);

#pragma unroll 2
    for (int j = beg; j < end; j++) {
        int s = g_srcs[j];
        float w = g_ws[j];
        float2 xs = x2[s * 32 + lane];
        float wn = w;
        if (PLAST) {
            float2 es = e2[s * 32 + lane];
            float pp = xs.x * et.x + xs.y * et.y;
            float pm = xt.x * es.x + xt.y * es.y;
#pragma unroll
            for (int o = 16; o > 0; o >>= 1) {
                pp += __shfl_xor_sync(0xffffffffu, pp, o);
                pm += __shfl_xor_sync(0xffffffffu, pm, o);
            }
            wn = w + DT * (ep * pp - em * pm - LAMBDA_W * w);
            if (lane == 0) g_ws[j] = wn;
        }
        if (MSG) {
            macc.x += wn * xs.x;
            macc.y += wn * xs.y;
        }
    }

    if (MSG) {
        ((float2*)g_msg)[node * 32 + lane] = macc;
    }
}

// ---------------- node kernel: fused concat + MLP + x/e integration ----------------
#define NT 128
#define NTH 512
#define SH_PAD 132
#define SMEM_FLOATS (HID * HID + HID * DIM + HID + DIM + NT * SH_PAD + NT * DIM)
#define SMEM_BYTES (SMEM_FLOATS * 4)

__global__ void __launch_bounds__(NTH) node_kernel(const float* __restrict__ W1,
                                                   const float* __restrict__ b1,
                                                   const float* __restrict__ W2,
                                                   const float* __restrict__ b2) {
    extern __shared__ float smem[];
    float* sW1 = smem;                  // [128][128]
    float* sW2 = sW1 + HID * HID;       // [128][64]
    float* sB1 = sW2 + HID * DIM;       // [128]
    float* sB2 = sB1 + HID;             // [64]
    float* sH  = sB2 + DIM;             // [NT][132]
    float* sF  = sH + NT * SH_PAD;      // [NT][64]

    int tid = threadIdx.x;
    int base = blockIdx.x * NT;

    {
        const float4* s4 = (const float4*)W1;
        float4* d4 = (float4*)sW1;
        for (int i = tid; i < HID * HID / 4; i += NTH) d4[i] = s4[i];
        const float4* s2 = (const float4*)W2;
        float4* d2 = (float4*)sW2;
        for (int i = tid; i < HID * DIM / 4; i += NTH) d2[i] = s2[i];
        if (tid < HID) sB1[tid] = b1[tid];
        else if (tid >= HID && tid < HID + DIM) sB2[tid - HID] = b2[tid - HID];
    }

    for (int i = tid; i < NT * HID; i += NTH) {
        int n = i >> 7;
        int c = i & 127;
        int node = base + n;
        float v = 0.0f;
        if (node < N_NODES)
            v = (c < DIM) ? g_x[node * DIM + c] : g_msg[node * DIM + (c - DIM)];
        sH[n * SH_PAD + c] = v;
    }
    __syncthreads();

    int jg = tid & 15;
    int ng = tid >> 4;
    int j0 = jg * 8;
    int n0 = ng * 4;

    float acc[4][8];
#pragma unroll
    for (int i = 0; i < 4; i++)
#pragma unroll
        for (int u = 0; u < 8; u++) acc[i][u] = sB1[j0 + u];

#pragma unroll 4
    for (int k = 0; k < HID; k++) {
        float a0 = sH[(n0 + 0) * SH_PAD + k];
        float a1 = sH[(n0 + 1) * SH_PAD + k];
        float a2 = sH[(n0 + 2) * SH_PAD + k];
        float a3 = sH[(n0 + 3) * SH_PAD + k];
        float4 wA = *(const float4*)&sW1[k * HID + j0];
        float4 wB = *(const float4*)&sW1[k * HID + j0 + 4];
        float a[4] = {a0, a1, a2, a3};
#pragma unroll
        for (int i = 0; i < 4; i++) {
            acc[i][0] += a[i] * wA.x; acc[i][1] += a[i] * wA.y;
            acc[i][2] += a[i] * wA.z; acc[i][3] += a[i] * wA.w;
            acc[i][4] += a[i] * wB.x; acc[i][5] += a[i] * wB.y;
            acc[i][6] += a[i] * wB.z; acc[i][7] += a[i] * wB.w;
        }
    }
    __syncthreads();

#pragma unroll
    for (int i = 0; i < 4; i++) {
        float4 vA = make_float4(fmaxf(acc[i][0], 0.f), fmaxf(acc[i][1], 0.f),
                                fmaxf(acc[i][2], 0.f), fmaxf(acc[i][3], 0.f));
        float4 vB = make_float4(fmaxf(acc[i][4], 0.f), fmaxf(acc[i][5], 0.f),
                                fmaxf(acc[i][6], 0.f), fmaxf(acc[i][7], 0.f));
        *(float4*)&sH[(n0 + i) * SH_PAD + j0] = vA;
        *(float4*)&sH[(n0 + i) * SH_PAD + j0 + 4] = vB;
    }
    __syncthreads();

    int dg = tid & 15;
    int d0 = dg * 4;
    float f[4][4];
#pragma unroll
    for (int i = 0; i < 4; i++)
#pragma unroll
        for (int u = 0; u < 4; u++) f[i][u] = sB2[d0 + u];

#pragma unroll 4
    for (int k = 0; k < HID; k++) {
        float a0 = sH[(n0 + 0) * SH_PAD + k];
        float a1 = sH[(n0 + 1) * SH_PAD + k];
        float a2 = sH[(n0 + 2) * SH_PAD + k];
        float a3 = sH[(n0 + 3) * SH_PAD + k];
        float4 wv = *(const float4*)&sW2[k * DIM + d0];
        float a[4] = {a0, a1, a2, a3};
#pragma unroll
        for (int i = 0; i < 4; i++) {
            f[i][0] += a[i] * wv.x; f[i][1] += a[i] * wv.y;
            f[i][2] += a[i] * wv.z; f[i][3] += a[i] * wv.w;
        }
    }
#pragma unroll
    for (int i = 0; i < 4; i++)
        *(float4*)&sF[(n0 + i) * DIM + d0] =
            make_float4(f[i][0], f[i][1], f[i][2], f[i][3]);
    __syncthreads();

    for (int i = tid; i < NT * DIM; i += NTH) {
        int n = i >> 6;
        int node = base + n;
        if (node < N_NODES) {
            int d = i & 63;
            int gi = node * DIM + d;
            float xv = g_x[gi];
            float fv = sF[n * DIM + d];
            float xn = xv + DT * (fv - xv);
            g_x[gi] = xn;
            float ev = g_e[gi];
            g_e[gi] = ev + DT * (xn - ev * (1.0f / TAU));
        }
    }
}

// ---------------- output: [x (3.2M) | w (0.8M, original order via perm)] -----------
__global__ void finalize_kernel(float* __restrict__ out) {
    int i = blockIdx.x * blockDim.x + threadIdx.x;
    if (i < N_NODES * DIM) {
        out[i] = g_x[i];
    } else if (i < N_NODES * DIM + N_EDGES) {
        int j = i - N_NODES * DIM;
        out[N_NODES * DIM + g_perm[j]] = g_ws[j];
    }
}

// ---------------- launch ------------------------------------------------------------
extern "C" void kernel_launch(void* const* d_in, const int* in_sizes, int n_in,
                              void* d_out, int out_size) {
    const float* x_in  = (const float*)d_in[0];
    const void*  ei    = d_in[1];
    const float* ea    = (const float*)d_in[2];
    const float* etap  = (const float*)d_in[3];
    const float* etam  = (const float*)d_in[4];
    const float* W1    = (const float*)d_in[5];
    const float* b1    = (const float*)d_in[6];
    const float* W2    = (const float*)d_in[7];
    const float* b2    = (const float*)d_in[8];

    cudaFuncSetAttribute(node_kernel, cudaFuncAttributeMaxDynamicSharedMemorySize,
                         SMEM_BYTES);

    const int EBLK = (N_NODES + 7) / 8;       // warp per node, 8 warps/block
    const int NBLK = (N_NODES + NT - 1) / NT; // 391

    // ---- one-time CSR build ----
    detect_kernel<<<1, 32>>>((const int*)ei);
    zero_kernel<<<(N_NODES + 255) / 256, 256>>>();
    convert_kernel<<<(N_EDGES + 255) / 256, 256>>>(ei);
    scan_kernel<<<1, 1024>>>();
    scatter_kernel<<<(N_EDGES + 255) / 256, 256>>>(ea);
    init_nodes_kernel<<<(N_NODES * DIM + 255) / 256, 256>>>(x_in);

    // step 0: messages only
    edge_csr_kernel<false, true><<<EBLK, 256>>>(etap, etam);
    node_kernel<<<NBLK, NTH, SMEM_BYTES>>>(W1, b1, W2, b2);

    // steps 1..9: previous step's plasticity fused with this step's messages
    for (int t = 1; t < N_STEPS; t++) {
        edge_csr_kernel<true, true><<<EBLK, 256>>>(etap, etam);
        node_kernel<<<NBLK, NTH, SMEM_BYTES>>>(W1, b1, W2, b2);
    }
    // final plasticity (w_10)
    edge_csr_kernel<true, false><<<EBLK, 256>>>(etap, etam);

    finalize_kernel<<<(N_NODES * DIM + N_EDGES + 255) / 256, 256>>>((float*)d_out);
}

// round 5
// speedup vs baseline: 1.0454x; 1.0454x over previous
#include <cuda_runtime.h>
#include <cstdint>

#define N_NODES 50000
#define N_EDGES 800000
#define DIM 64
#define HID 128
#define DT 0.1f
#define TAU 2.0f
#define LAMBDA_W 1e-4f
#define N_STEPS 10

// ---------------- scratch (device globals; no allocations allowed) ----------------
__device__ float g_x[N_NODES * DIM];
__device__ float g_e[N_NODES * DIM];
__device__ float g_msg[N_NODES * DIM];
__device__ float g_w[N_EDGES];
__device__ int2  g_edge[N_EDGES];
__device__ int   g_is64;

// ---------------- dtype detection for edge_index (int32 vs int64) -----------------
__global__ void detect_kernel(const int* __restrict__ ei32) {
    int v = ei32[2 * threadIdx.x + 1];
    unsigned nz = __ballot_sync(0xffffffffu, v != 0);
    if (threadIdx.x == 0) g_is64 = (nz == 0u) ? 1 : 0;
}

__global__ void convert_kernel(const void* __restrict__ ei, const float* __restrict__ w_in) {
    int i = blockIdx.x * blockDim.x + threadIdx.x;
    if (i >= N_EDGES) return;
    int s, t;
    if (g_is64) {
        const long long* p = (const long long*)ei;
        s = (int)p[i];
        t = (int)p[N_EDGES + i];
    } else {
        const int* p = (const int*)ei;
        s = p[i];
        t = p[N_EDGES + i];
    }
    g_edge[i] = make_int2(s, t);
    g_w[i] = w_in[i];
}

__global__ void init_nodes_kernel(const float* __restrict__ x_in) {
    int i = blockIdx.x * blockDim.x + threadIdx.x;
    if (i < N_NODES * DIM) {
        g_x[i] = x_in[i];
        g_e[i] = 0.0f;
        g_msg[i] = 0.0f;
    }
}

// ---------------- fused edge kernel: plasticity (step t) + messages (step t+1) ----
// 16 threads per edge, each owns 4 dims (float4). 2 edges per warp. (R1-proven.)
template <bool PLAST, bool MSG>
__global__ void __launch_bounds__(256) edge_kernel(const float* __restrict__ etap,
                                                   const float* __restrict__ etam) {
    int gt = blockIdx.x * 256 + threadIdx.x;
    int eidx = gt >> 4;  // grid sized exactly: N_EDGES*16 threads
    int sub = gt & 15;

    int2 st = g_edge[eidx];
    float w = g_w[eidx];
    const float4* x4 = (const float4*)g_x;
    float4 xs = x4[st.x * 16 + sub];
    float wn = w;

    if (PLAST) {
        const float4* e4 = (const float4*)g_e;
        float4 xt = x4[st.y * 16 + sub];
        float4 es = e4[st.x * 16 + sub];
        float4 et = e4[st.y * 16 + sub];
        float pp = xs.x * et.x + xs.y * et.y + xs.z * et.z + xs.w * et.w;
        float pm = xt.x * es.x + xt.y * es.y + xt.z * es.z + xt.w * es.w;
#pragma unroll
        for (int o = 8; o > 0; o >>= 1) {
            pp += __shfl_xor_sync(0xffffffffu, pp, o);
            pm += __shfl_xor_sync(0xffffffffu, pm, o);
        }
        float ep = __ldg(etap);
        float em = __ldg(etam);
        wn = w + DT * (ep * pp - em * pm - LAMBDA_W * w);
        if (sub == 0) g_w[eidx] = wn;
    }

    if (MSG) {
        float* dst = &g_msg[st.y * DIM + sub * 4];
        asm volatile("red.global.add.v4.f32 [%0], {%1,%2,%3,%4};"
                     :: "l"(dst), "f"(wn * xs.x), "f"(wn * xs.y),
                        "f"(wn * xs.z), "f"(wn * xs.w)
                     : "memory");
    }
}

// ---------------- tf32 tensor-core node kernel ------------------------------------
// 128 nodes/block, 256 threads (8 warps). Warp w owns rows [16w,16w+16) through
// both layers. Split-precision tf32 (3xTF32): hi*hi + hi*lo + lo*hi ~ fp32.
#define NT 128
#define NTH 256
#define KP 132  // padded row stride (floats): conflict-free fragment LDS

__device__ __forceinline__ uint32_t f2tf(float x) {
    uint32_t r;
    asm("cvt.rna.tf32.f32 %0, %1;" : "=r"(r) : "f"(x));
    return r;
}
__device__ __forceinline__ void split_tf(float v, uint32_t& hi, uint32_t& lo) {
    hi = f2tf(v);
    lo = f2tf(v - __uint_as_float(hi));
}
__device__ __forceinline__ void mma_tf32(float c[4], uint32_t a0, uint32_t a1,
                                         uint32_t a2, uint32_t a3,
                                         uint32_t b0, uint32_t b1) {
    asm volatile(
        "mma.sync.aligned.m16n8k8.row.col.f32.tf32.tf32.f32 "
        "{%0,%1,%2,%3}, {%4,%5,%6,%7}, {%8,%9}, {%0,%1,%2,%3};"
        : "+f"(c[0]), "+f"(c[1]), "+f"(c[2]), "+f"(c[3])
        : "r"(a0), "r"(a1), "r"(a2), "r"(a3), "r"(b0), "r"(b1));
}

// smem: W1t [128][KP], W2t [64][KP], A [128][KP], b1[128], b2[64]
#define SM_W1T 0
#define SM_W2T (SM_W1T + HID * KP)
#define SM_A   (SM_W2T + DIM * KP)
#define SM_B1  (SM_A + NT * KP)
#define SM_B2  (SM_B1 + HID)
#define SMEM_FLOATS (SM_B2 + DIM)
#define SMEM_BYTES (SMEM_FLOATS * 4)

__global__ void __launch_bounds__(NTH, 1) node_kernel(const float* __restrict__ W1,
                                                      const float* __restrict__ b1,
                                                      const float* __restrict__ W2,
                                                      const float* __restrict__ b2) {
    extern __shared__ float smem[];
    float* sW1t = smem + SM_W1T;  // [n][k] = W1[k][n]
    float* sW2t = smem + SM_W2T;  // [n][k] = W2[k][n]
    float* sA   = smem + SM_A;    // [row][k]
    float* sB1  = smem + SM_B1;
    float* sB2  = smem + SM_B2;

    int tid = threadIdx.x;
    int base = blockIdx.x * NT;

    // ---- stage weights (transposed) + biases + input A = [x | msg] ----
    for (int i = tid; i < HID * HID; i += NTH) {
        int k = i >> 7, n = i & 127;
        sW1t[n * KP + k] = W1[i];
    }
    for (int i = tid; i < HID * DIM; i += NTH) {
        int k = i >> 6, n = i & 63;
        sW2t[n * KP + k] = W2[i];
    }
    if (tid < HID) sB1[tid] = b1[tid];
    if (tid >= HID && tid < HID + DIM) sB2[tid - HID] = b2[tid - HID];

    for (int i = tid; i < NT * HID; i += NTH) {
        int r = i >> 7, c = i & 127;
        int node = base + r;
        float v = 0.0f;
        if (node < N_NODES)
            v = (c < DIM) ? g_x[node * DIM + c] : g_msg[node * DIM + (c - DIM)];
        sA[r * KP + c] = v;
    }
    __syncthreads();

    int warp = tid >> 5;
    int lane = tid & 31;
    int gq = lane >> 2;   // group id 0..7
    int tq = lane & 3;    // thread in group 0..3
    int m0 = warp * 16;

    // =================== layer 1: C1 = relu(A @ W1 + b1), N=128 ===================
    {
        float c[16][4];
#pragma unroll
        for (int nt = 0; nt < 16; nt++) {
            c[nt][0] = sB1[nt * 8 + 2 * tq];
            c[nt][1] = sB1[nt * 8 + 2 * tq + 1];
            c[nt][2] = c[nt][0];
            c[nt][3] = c[nt][1];
        }
#pragma unroll 2
        for (int kk = 0; kk < 16; kk++) {
            int k0 = kk * 8;
            uint32_t ah[4], al[4];
            split_tf(sA[(m0 + gq) * KP + k0 + tq],         ah[0], al[0]);
            split_tf(sA[(m0 + gq + 8) * KP + k0 + tq],     ah[1], al[1]);
            split_tf(sA[(m0 + gq) * KP + k0 + tq + 4],     ah[2], al[2]);
            split_tf(sA[(m0 + gq + 8) * KP + k0 + tq + 4], ah[3], al[3]);
#pragma unroll
            for (int nt = 0; nt < 16; nt++) {
                uint32_t bh0, bl0, bh1, bl1;
                split_tf(sW1t[(nt * 8 + gq) * KP + k0 + tq],     bh0, bl0);
                split_tf(sW1t[(nt * 8 + gq) * KP + k0 + tq + 4], bh1, bl1);
                mma_tf32(c[nt], ah[0], ah[1], ah[2], ah[3], bh0, bh1);
                mma_tf32(c[nt], ah[0], ah[1], ah[2], ah[3], bl0, bl1);
                mma_tf32(c[nt], al[0], al[1], al[2], al[3], bh0, bh1);
            }
        }
        // relu -> write back to own rows of sA (A2)
        __syncwarp();
#pragma unroll
        for (int nt = 0; nt < 16; nt++) {
            int col = nt * 8 + 2 * tq;
            float2 lo = make_float2(fmaxf(c[nt][0], 0.f), fmaxf(c[nt][1], 0.f));
            float2 hi = make_float2(fmaxf(c[nt][2], 0.f), fmaxf(c[nt][3], 0.f));
            *(float2*)&sA[(m0 + gq) * KP + col] = lo;
            *(float2*)&sA[(m0 + gq + 8) * KP + col] = hi;
        }
        __syncwarp();
    }

    // =================== layer 2: F = A2 @ W2 + b2, N=64 ==========================
    {
        float c[8][4];
#pragma unroll
        for (int nt = 0; nt < 8; nt++) {
            c[nt][0] = sB2[nt * 8 + 2 * tq];
            c[nt][1] = sB2[nt * 8 + 2 * tq + 1];
            c[nt][2] = c[nt][0];
            c[nt][3] = c[nt][1];
        }
#pragma unroll 2
        for (int kk = 0; kk < 16; kk++) {
            int k0 = kk * 8;
            uint32_t ah[4], al[4];
            split_tf(sA[(m0 + gq) * KP + k0 + tq],         ah[0], al[0]);
            split_tf(sA[(m0 + gq + 8) * KP + k0 + tq],     ah[1], al[1]);
            split_tf(sA[(m0 + gq) * KP + k0 + tq + 4],     ah[2], al[2]);
            split_tf(sA[(m0 + gq + 8) * KP + k0 + tq + 4], ah[3], al[3]);
#pragma unroll
            for (int nt = 0; nt < 8; nt++) {
                uint32_t bh0, bl0, bh1, bl1;
                split_tf(sW2t[(nt * 8 + gq) * KP + k0 + tq],     bh0, bl0);
                split_tf(sW2t[(nt * 8 + gq) * KP + k0 + tq + 4], bh1, bl1);
                mma_tf32(c[nt], ah[0], ah[1], ah[2], ah[3], bh0, bh1);
                mma_tf32(c[nt], ah[0], ah[1], ah[2], ah[3], bl0, bl1);
                mma_tf32(c[nt], al[0], al[1], al[2], al[3], bh0, bh1);
            }
        }
        // write F into own rows of sA cols [0,64)
        __syncwarp();
#pragma unroll
        for (int nt = 0; nt < 8; nt++) {
            int col = nt * 8 + 2 * tq;
            *(float2*)&sA[(m0 + gq) * KP + col] = make_float2(c[nt][0], c[nt][1]);
            *(float2*)&sA[(m0 + gq + 8) * KP + col] = make_float2(c[nt][2], c[nt][3]);
        }
        __syncwarp();
    }

    // ---- epilogue (per warp, own 16 rows): x += DT*(f-x); e update; zero msg ----
#pragma unroll
    for (int i = 0; i < 32; i++) {
        int flat = i * 32 + lane;          // over [16][64]
        int r = flat >> 6, d = flat & 63;
        int node = base + m0 + r;
        if (node < N_NODES) {
            int gi = node * DIM + d;
            float xv = g_x[gi];
            float fv = sA[(m0 + r) * KP + d];
            float xn = xv + DT * (fv - xv);
            g_x[gi] = xn;
            float ev = g_e[gi];
            g_e[gi] = ev + DT * (xn - ev * (1.0f / TAU));
            g_msg[gi] = 0.0f;
        }
    }
}

// ---------------- output: [x (3.2M) | w (0.8M)] -----------------------------------
__global__ void finalize_kernel(float* __restrict__ out) {
    int i = blockIdx.x * blockDim.x + threadIdx.x;
    if (i < N_NODES * DIM) out[i] = g_x[i];
    else if (i < N_NODES * DIM + N_EDGES) out[i] = g_w[i - N_NODES * DIM];
}

// ---------------- launch ------------------------------------------------------------
extern "C" void kernel_launch(void* const* d_in, const int* in_sizes, int n_in,
                              void* d_out, int out_size) {
    const float* x_in  = (const float*)d_in[0];
    const void*  ei    = d_in[1];
    const float* ea    = (const float*)d_in[2];
    const float* etap  = (const float*)d_in[3];
    const float* etam  = (const float*)d_in[4];
    const float* W1    = (const float*)d_in[5];
    const float* b1    = (const float*)d_in[6];
    const float* W2    = (const float*)d_in[7];
    const float* b2    = (const float*)d_in[8];

    cudaFuncSetAttribute(node_kernel, cudaFuncAttributeMaxDynamicSharedMemorySize,
                         SMEM_BYTES);

    const int EBLK = (N_EDGES * 16) / 256;            // 50000, exact
    const int NBLK = (N_NODES + NT - 1) / NT;         // 391

    detect_kernel<<<1, 32>>>((const int*)ei);
    convert_kernel<<<(N_EDGES + 255) / 256, 256>>>(ei, ea);
    init_nodes_kernel<<<(N_NODES * DIM + 255) / 256, 256>>>(x_in);

    // step 0: messages only (no plasticity yet)
    edge_kernel<false, true><<<EBLK, 256>>>(etap, etam);
    node_kernel<<<NBLK, NTH, SMEM_BYTES>>>(W1, b1, W2, b2);

    // steps 1..9: plasticity of previous step fused with this step's messages
    for (int t = 1; t < N_STEPS; t++) {
        edge_kernel<true, true><<<EBLK, 256>>>(etap, etam);
        node_kernel<<<NBLK, NTH, SMEM_BYTES>>>(W1, b1, W2, b2);
    }
    // final plasticity (w_10), no messages needed
    edge_kernel<true, false><<<EBLK, 256>>>(etap, etam);

    finalize_kernel<<<(N_NODES * DIM + N_EDGES + 255) / 256, 256>>>((float*)d_out);
}

// round 7
// speedup vs baseline: 1.1486x; 1.0988x over previous
#include <cuda_runtime.h>
#include <cstdint>

#define N_NODES 50000
#define N_EDGES 800000
#define DIM 64
#define HID 128
#define DT 0.1f
#define TAU 2.0f
#define LAMBDA_W 1e-4f
#define N_STEPS 10

// ---------------- scratch (device globals; no allocations allowed) ----------------
__device__ float g_x[N_NODES * DIM];
__device__ float g_e[N_NODES * DIM];
__device__ float g_msg[N_NODES * DIM];
__device__ float g_w[N_EDGES];
__device__ int2  g_edge[N_EDGES];
// pre-split, pre-transposed, pre-swizzled weights (tf32 hi|lo)
__device__ uint32_t g_wsplit1[2 * HID * HID];   // [hi: n*128+sw(k)] [lo: +16384]
__device__ uint32_t g_wsplit2[2 * DIM * HID];   // [hi: n*128+sw(k)] [lo: +8192]

__device__ __forceinline__ uint32_t f2tf(float x) {
    uint32_t r;
    asm("cvt.rna.tf32.f32 %0, %1;" : "=r"(r) : "f"(x));
    return r;
}
__device__ __forceinline__ void split_tf(float v, uint32_t& hi, uint32_t& lo) {
    hi = f2tf(v);
    lo = f2tf(v - __uint_as_float(hi));
}
__device__ __forceinline__ void mma_tf32(float c[4], uint32_t a0, uint32_t a1,
                                         uint32_t a2, uint32_t a3,
                                         uint32_t b0, uint32_t b1) {
    asm volatile(
        "mma.sync.aligned.m16n8k8.row.col.f32.tf32.tf32.f32 "
        "{%0,%1,%2,%3}, {%4,%5,%6,%7}, {%8,%9}, {%0,%1,%2,%3};"
        : "+f"(c[0]), "+f"(c[1]), "+f"(c[2]), "+f"(c[3])
        : "r"(a0), "r"(a1), "r"(a2), "r"(a3), "r"(b0), "r"(b1));
}

// ---------------- fused convert + init (detection done per-block) ------------------
__global__ void convert_init_kernel(const void* __restrict__ ei,
                                    const float* __restrict__ w_in,
                                    const float* __restrict__ x_in) {
    __shared__ int s_is64;
    if (threadIdx.x < 32) {
        int v = ((const int*)ei)[2 * threadIdx.x + 1];
        unsigned nz = __ballot_sync(0xffffffffu, v != 0);
        if (threadIdx.x == 0) s_is64 = (nz == 0u) ? 1 : 0;
    }
    __syncthreads();
    int i = blockIdx.x * blockDim.x + threadIdx.x;
    if (i < N_EDGES) {
        int s, t;
        if (s_is64) {
            const long long* p = (const long long*)ei;
            s = (int)p[i];
            t = (int)p[N_EDGES + i];
        } else {
            const int* p = (const int*)ei;
            s = p[i];
            t = p[N_EDGES + i];
        }
        g_edge[i] = make_int2(s, t);
        g_w[i] = w_in[i];
    }
    if (i < N_NODES * DIM) {
        g_x[i] = x_in[i];
        g_e[i] = 0.0f;
        g_msg[i] = 0.0f;
    }
}

// ---------------- one-time weight prep: transpose + split + swizzle ---------------
__global__ void prep_weights_kernel(const float* __restrict__ W1,
                                    const float* __restrict__ W2) {
    int i = blockIdx.x * blockDim.x + threadIdx.x;
    if (i < HID * HID) {                     // W1 [k=2D=128][n=H=128]
        int n = i >> 7, k = i & 127;
        float v = W1[k * HID + n];
        uint32_t hi, lo;
        split_tf(v, hi, lo);
        int sw = k ^ ((n & 7) << 2);
        g_wsplit1[n * 128 + sw] = hi;
        g_wsplit1[HID * HID + n * 128 + sw] = lo;
    } else if (i < HID * HID + DIM * HID) {  // W2 [k=H=128][n=D=64]
        int j = i - HID * HID;
        int n = j >> 7, k = j & 127;
        float v = W2[k * DIM + n];
        uint32_t hi, lo;
        split_tf(v, hi, lo);
        int sw = k ^ ((n & 7) << 2);
        g_wsplit2[n * 128 + sw] = hi;
        g_wsplit2[DIM * HID + n * 128 + sw] = lo;
    }
}

// ---------------- fused edge kernel (R1-proven) ------------------------------------
template <bool PLAST, bool MSG>
__global__ void __launch_bounds__(256) edge_kernel(const float* __restrict__ etap,
                                                   const float* __restrict__ etam) {
    int gt = blockIdx.x * 256 + threadIdx.x;
    int eidx = gt >> 4;
    int sub = gt & 15;

    int2 st = g_edge[eidx];
    float w = g_w[eidx];
    const float4* x4 = (const float4*)g_x;
    float4 xs = x4[st.x * 16 + sub];
    float wn = w;

    if (PLAST) {
        const float4* e4 = (const float4*)g_e;
        float4 xt = x4[st.y * 16 + sub];
        float4 es = e4[st.x * 16 + sub];
        float4 et = e4[st.y * 16 + sub];
        float pp = xs.x * et.x + xs.y * et.y + xs.z * et.z + xs.w * et.w;
        float pm = xt.x * es.x + xt.y * es.y + xt.z * es.z + xt.w * es.w;
#pragma unroll
        for (int o = 8; o > 0; o >>= 1) {
            pp += __shfl_xor_sync(0xffffffffu, pp, o);
            pm += __shfl_xor_sync(0xffffffffu, pm, o);
        }
        float ep = __ldg(etap);
        float em = __ldg(etam);
        wn = w + DT * (ep * pp - em * pm - LAMBDA_W * w);
        if (sub == 0) g_w[eidx] = wn;
    }

    if (MSG) {
        float* dst = &g_msg[st.y * DIM + sub * 4];
        asm volatile("red.global.add.v4.f32 [%0], {%1,%2,%3,%4};"
                     :: "l"(dst), "f"(wn * xs.x), "f"(wn * xs.y),
                        "f"(wn * xs.z), "f"(wn * xs.w)
                     : "memory");
    }
}

// ---------------- tf32 node kernel v2: pre-split weights, stage-overwrite ---------
// 128 nodes/block, 256 threads (8 warps); warp owns 16 rows through both layers.
#define NT 128
#define NTH 256
#define KP 132                       // A row stride (floats)
#define WBUF_U32 (2 * HID * HID)     // 32768 u32 = 128KB (holds W1 hi|lo, later W2)
// smem (floats): WBUF | A[128][132] | b1[128] | b2[64]
#define SM_A   WBUF_U32
#define SM_B1  (SM_A + NT * KP)
#define SM_B2  (SM_B1 + HID)
#define SMEM_FLOATS (SM_B2 + DIM)
#define SMEM_BYTES (SMEM_FLOATS * 4)

__global__ void __launch_bounds__(NTH, 1) node_kernel(const float* __restrict__ b1,
                                                      const float* __restrict__ b2) {
    extern __shared__ uint32_t smu[];
    uint32_t* wb = smu;                       // weight buffer (hi | lo)
    float* sA  = (float*)(smu + SM_A);        // [row][KP]
    float* sB1 = (float*)(smu + SM_B1);
    float* sB2 = (float*)(smu + SM_B2);

    int tid = threadIdx.x;
    int base = blockIdx.x * NT;

    // ---- stage W1 hi/lo (straight uint4 copy; already transposed+swizzled) ----
    {
        const uint4* src = (const uint4*)g_wsplit1;
        uint4* dst = (uint4*)wb;
#pragma unroll
        for (int i = 0; i < WBUF_U32 / 4 / NTH; i++)
            dst[i * NTH + tid] = src[i * NTH + tid];
    }
    if (tid < HID) sB1[tid] = b1[tid];
    if (tid >= HID && tid < HID + DIM) sB2[tid - HID] = b2[tid - HID];

    // ---- stage A = [x | msg] ----
    for (int i = tid; i < NT * HID; i += NTH) {
        int r = i >> 7, c = i & 127;
        int node = base + r;
        float v = 0.0f;
        if (node < N_NODES)
            v = (c < DIM) ? g_x[node * DIM + c] : g_msg[node * DIM + (c - DIM)];
        sA[r * KP + c] = v;
    }
    __syncthreads();

    int warp = tid >> 5;
    int lane = tid & 31;
    int gq = lane >> 2;        // 0..7
    int tq = lane & 3;         // 0..3
    int m0 = warp * 16;
    int cx = gq << 2;          // swizzle XOR constant
    int rb = gq * 128;         // row base within 8-row group

    // =================== layer 1: C1 = relu(A @ W1 + b1), N=128 ===================
    {
        float c[16][4];
#pragma unroll
        for (int nt = 0; nt < 16; nt++) {
            c[nt][0] = sB1[nt * 8 + 2 * tq];
            c[nt][1] = sB1[nt * 8 + 2 * tq + 1];
            c[nt][2] = c[nt][0];
            c[nt][3] = c[nt][1];
        }
#pragma unroll 4
        for (int kk = 0; kk < 16; kk++) {
            int k0 = kk * 8;
            uint32_t ah[4], al[4];
            split_tf(sA[(m0 + gq) * KP + k0 + tq],         ah[0], al[0]);
            split_tf(sA[(m0 + gq + 8) * KP + k0 + tq],     ah[1], al[1]);
            split_tf(sA[(m0 + gq) * KP + k0 + tq + 4],     ah[2], al[2]);
            split_tf(sA[(m0 + gq + 8) * KP + k0 + tq + 4], ah[3], al[3]);
            int p0 = (k0 + tq) ^ cx;
            int p1 = (k0 + tq + 4) ^ cx;
#pragma unroll
            for (int nt = 0; nt < 16; nt++) {
                int rbase = nt * 1024 + rb;
                uint32_t bh0 = wb[rbase + p0];
                uint32_t bh1 = wb[rbase + p1];
                uint32_t bl0 = wb[HID * HID + rbase + p0];
                uint32_t bl1 = wb[HID * HID + rbase + p1];
                mma_tf32(c[nt], ah[0], ah[1], ah[2], ah[3], bh0, bh1);
                mma_tf32(c[nt], ah[0], ah[1], ah[2], ah[3], bl0, bl1);
                mma_tf32(c[nt], al[0], al[1], al[2], al[3], bh0, bh1);
            }
        }
        __syncwarp();
#pragma unroll
        for (int nt = 0; nt < 16; nt++) {
            int col = nt * 8 + 2 * tq;
            *(float2*)&sA[(m0 + gq) * KP + col] =
                make_float2(fmaxf(c[nt][0], 0.f), fmaxf(c[nt][1], 0.f));
            *(float2*)&sA[(m0 + gq + 8) * KP + col] =
                make_float2(fmaxf(c[nt][2], 0.f), fmaxf(c[nt][3], 0.f));
        }
    }
    __syncthreads();

    // ---- overwrite weight buffer with W2 hi/lo ----
    {
        const uint4* src = (const uint4*)g_wsplit2;
        uint4* dst = (uint4*)wb;
#pragma unroll
        for (int i = 0; i < (2 * DIM * HID) / 4 / NTH; i++)
            dst[i * NTH + tid] = src[i * NTH + tid];
    }
    __syncthreads();

    // =================== layer 2: F = A2 @ W2 + b2, N=64 ==========================
    {
        float c[8][4];
#pragma unroll
        for (int nt = 0; nt < 8; nt++) {
            c[nt][0] = sB2[nt * 8 + 2 * tq];
            c[nt][1] = sB2[nt * 8 + 2 * tq + 1];
            c[nt][2] = c[nt][0];
            c[nt][3] = c[nt][1];
        }
#pragma unroll 4
        for (int kk = 0; kk < 16; kk++) {
            int k0 = kk * 8;
            uint32_t ah[4], al[4];
            split_tf(sA[(m0 + gq) * KP + k0 + tq],         ah[0], al[0]);
            split_tf(sA[(m0 + gq + 8) * KP + k0 + tq],     ah[1], al[1]);
            split_tf(sA[(m0 + gq) * KP + k0 + tq + 4],     ah[2], al[2]);
            split_tf(sA[(m0 + gq + 8) * KP + k0 + tq + 4], ah[3], al[3]);
            int p0 = (k0 + tq) ^ cx;
            int p1 = (k0 + tq + 4) ^ cx;
#pragma unroll
            for (int nt = 0; nt < 8; nt++) {
                int rbase = nt * 1024 + rb;
                uint32_t bh0 = wb[rbase + p0];
                uint32_t bh1 = wb[rbase + p1];
                uint32_t bl0 = wb[DIM * HID + rbase + p0];
                uint32_t bl1 = wb[DIM * HID + rbase + p1];
                mma_tf32(c[nt], ah[0], ah[1], ah[2], ah[3], bh0, bh1);
                mma_tf32(c[nt], ah[0], ah[1], ah[2], ah[3], bl0, bl1);
                mma_tf32(c[nt], al[0], al[1], al[2], al[3], bh0, bh1);
            }
        }
        __syncwarp();
#pragma unroll
        for (int nt = 0; nt < 8; nt++) {
            int col = nt * 8 + 2 * tq;
            *(float2*)&sA[(m0 + gq) * KP + col] = make_float2(c[nt][0], c[nt][1]);
            *(float2*)&sA[(m0 + gq + 8) * KP + col] = make_float2(c[nt][2], c[nt][3]);
        }
        __syncwarp();
    }

    // ---- epilogue (warp-local rows): x += DT*(f-x); e update; zero msg ----
#pragma unroll
    for (int i = 0; i < 32; i++) {
        int flat = i * 32 + lane;          // over [16][64]
        int r = flat >> 6, d = flat & 63;
        int node = base + m0 + r;
        if (node < N_NODES) {
            int gi = node * DIM + d;
            float xv = g_x[gi];
            float fv = sA[(m0 + r) * KP + d];
            float xn = xv + DT * (fv - xv);
            g_x[gi] = xn;
            float ev = g_e[gi];
            g_e[gi] = ev + DT * (xn - ev * (1.0f / TAU));
            g_msg[gi] = 0.0f;
        }
    }
}

// ---------------- output: [x (3.2M) | w (0.8M)] -----------------------------------
__global__ void finalize_kernel(float* __restrict__ out) {
    int i = blockIdx.x * blockDim.x + threadIdx.x;
    if (i < N_NODES * DIM) out[i] = g_x[i];
    else if (i < N_NODES * DIM + N_EDGES) out[i] = g_w[i - N_NODES * DIM];
}

// ---------------- launch ------------------------------------------------------------
extern "C" void kernel_launch(void* const* d_in, const int* in_sizes, int n_in,
                              void* d_out, int out_size) {
    const float* x_in  = (const float*)d_in[0];
    const void*  ei    = d_in[1];
    const float* ea    = (const float*)d_in[2];
    const float* etap  = (const float*)d_in[3];
    const float* etam  = (const float*)d_in[4];
    const float* W1    = (const float*)d_in[5];
    const float* b1    = (const float*)d_in[6];
    const float* W2    = (const float*)d_in[7];
    const float* b2    = (const float*)d_in[8];

    cudaFuncSetAttribute(node_kernel, cudaFuncAttributeMaxDynamicSharedMemorySize,
                         SMEM_BYTES);

    const int EBLK = (N_EDGES * 16) / 256;            // 50000
    const int NBLK = (N_NODES + NT - 1) / NT;         // 391

    // launch 0: convert + init (detection inside)
    convert_init_kernel<<<(N_NODES * DIM + 255) / 256, 256>>>(ei, ea, x_in);
    // launch 1: one-time weight split/transpose/swizzle
    prep_weights_kernel<<<(HID * HID + DIM * HID + 255) / 256, 256>>>(W1, W2);
    // launch 2: step-0 messages
    edge_kernel<false, true><<<EBLK, 256>>>(etap, etam);
    // launch 3 (ncu-profiled slot): node kernel
    node_kernel<<<NBLK, NTH, SMEM_BYTES>>>(b1, b2);

    for (int t = 1; t < N_STEPS; t++) {
        edge_kernel<true, true><<<EBLK, 256>>>(etap, etam);
        node_kernel<<<NBLK, NTH, SMEM_BYTES>>>(b1, b2);
    }
    edge_kernel<true, false><<<EBLK, 256>>>(etap, etam);

    finalize_kernel<<<(N_NODES * DIM + N_EDGES + 255) / 256, 256>>>((float*)d_out);
}

// round 8
// speedup vs baseline: 1.8514x; 1.6118x over previous
#include <cuda_runtime.h>
#include <cuda_bf16.h>
#include <cstdint>

#define N_NODES 50000
#define N_EDGES 800000
#define DIM 64
#define HID 128
#define DT 0.1f
#define TAU 2.0f
#define LAMBDA_W 1e-4f
#define N_STEPS 10

#define PADW 68  // u32 words per row (64 data + 4 pad): stride % 32 == 4 -> conflict-free frags

// ---------------- scratch (device globals; no allocations allowed) ----------------
__device__ float g_x[N_NODES * DIM];
__device__ float g_e[N_NODES * DIM];
__device__ float g_msg[N_NODES * DIM];
__device__ float g_w[N_EDGES];
__device__ int2  g_edge[N_EDGES];
// bf16-split weights, transposed [n][k/2] packed (low half = even k), padded rows
__device__ uint32_t g_w1t[2 * HID * PADW];   // plane0=hi, plane1=lo (stride HID*PADW)
__device__ uint32_t g_w2t[2 * DIM * PADW];

__device__ __forceinline__ uint32_t pack_split_hi(float a, float b) {
    __nv_bfloat162 t = __floats2bfloat162_rn(a, b);
    return *(uint32_t*)&t;
}
__device__ __forceinline__ void split2(float v, __nv_bfloat16& h, __nv_bfloat16& l) {
    h = __float2bfloat16_rn(v);
    l = __float2bfloat16_rn(v - __bfloat162float(h));
}
__device__ __forceinline__ uint32_t pack2(__nv_bfloat16 a, __nv_bfloat16 b) {
    __nv_bfloat162 t = __halves2bfloat162(a, b);
    return *(uint32_t*)&t;
}
__device__ __forceinline__ void mma_bf16(float c[4], uint32_t a0, uint32_t a1,
                                         uint32_t a2, uint32_t a3,
                                         uint32_t b0, uint32_t b1) {
    asm volatile(
        "mma.sync.aligned.m16n8k16.row.col.f32.bf16.bf16.f32 "
        "{%0,%1,%2,%3}, {%4,%5,%6,%7}, {%8,%9}, {%0,%1,%2,%3};"
        : "+f"(c[0]), "+f"(c[1]), "+f"(c[2]), "+f"(c[3])
        : "r"(a0), "r"(a1), "r"(a2), "r"(a3), "r"(b0), "r"(b1));
}

// ---------------- fused convert + init --------------------------------------------
__global__ void convert_init_kernel(const void* __restrict__ ei,
                                    const float* __restrict__ w_in,
                                    const float* __restrict__ x_in) {
    __shared__ int s_is64;
    if (threadIdx.x < 32) {
        int v = ((const int*)ei)[2 * threadIdx.x + 1];
        unsigned nz = __ballot_sync(0xffffffffu, v != 0);
        if (threadIdx.x == 0) s_is64 = (nz == 0u) ? 1 : 0;
    }
    __syncthreads();
    int i = blockIdx.x * blockDim.x + threadIdx.x;
    if (i < N_EDGES) {
        int s, t;
        if (s_is64) {
            const long long* p = (const long long*)ei;
            s = (int)p[i];
            t = (int)p[N_EDGES + i];
        } else {
            const int* p = (const int*)ei;
            s = p[i];
            t = p[N_EDGES + i];
        }
        g_edge[i] = make_int2(s, t);
        g_w[i] = w_in[i];
    }
    if (i < N_NODES * DIM) {
        g_x[i] = x_in[i];
        g_e[i] = 0.0f;
        g_msg[i] = 0.0f;
    }
}

// ---------------- one-time weight prep: transpose + bf16 split + pack + pad -------
__global__ void prep_weights_kernel(const float* __restrict__ W1,
                                    const float* __restrict__ W2) {
    int i = blockIdx.x * blockDim.x + threadIdx.x;
    if (i < HID * (HID / 2)) {               // W1 [k=128][n=128]
        int n = i >> 6, kp = i & 63;
        float v0 = W1[(2 * kp) * HID + n];
        float v1 = W1[(2 * kp + 1) * HID + n];
        __nv_bfloat16 h0, l0, h1, l1;
        split2(v0, h0, l0);
        split2(v1, h1, l1);
        g_w1t[n * PADW + kp] = pack2(h0, h1);
        g_w1t[HID * PADW + n * PADW + kp] = pack2(l0, l1);
    } else if (i < HID * (HID / 2) + DIM * (HID / 2)) {  // W2 [k=128][n=64]
        int j = i - HID * (HID / 2);
        int n = j >> 6, kp = j & 63;
        float v0 = W2[(2 * kp) * DIM + n];
        float v1 = W2[(2 * kp + 1) * DIM + n];
        __nv_bfloat16 h0, l0, h1, l1;
        split2(v0, h0, l0);
        split2(v1, h1, l1);
        g_w2t[n * PADW + kp] = pack2(h0, h1);
        g_w2t[DIM * PADW + n * PADW + kp] = pack2(l0, l1);
    }
}

// ---------------- fused edge kernel (R1-proven) ------------------------------------
template <bool PLAST, bool MSG>
__global__ void __launch_bounds__(256) edge_kernel(const float* __restrict__ etap,
                                                   const float* __restrict__ etam) {
    int gt = blockIdx.x * 256 + threadIdx.x;
    int eidx = gt >> 4;
    int sub = gt & 15;

    int2 st = g_edge[eidx];
    float w = g_w[eidx];
    const float4* x4 = (const float4*)g_x;
    float4 xs = x4[st.x * 16 + sub];
    float wn = w;

    if (PLAST) {
        const float4* e4 = (const float4*)g_e;
        float4 xt = x4[st.y * 16 + sub];
        float4 es = e4[st.x * 16 + sub];
        float4 et = e4[st.y * 16 + sub];
        float pp = xs.x * et.x + xs.y * et.y + xs.z * et.z + xs.w * et.w;
        float pm = xt.x * es.x + xt.y * es.y + xt.z * es.z + xt.w * es.w;
#pragma unroll
        for (int o = 8; o > 0; o >>= 1) {
            pp += __shfl_xor_sync(0xffffffffu, pp, o);
            pm += __shfl_xor_sync(0xffffffffu, pm, o);
        }
        float ep = __ldg(etap);
        float em = __ldg(etam);
        wn = w + DT * (ep * pp - em * pm - LAMBDA_W * w);
        if (sub == 0) g_w[eidx] = wn;
    }

    if (MSG) {
        float* dst = &g_msg[st.y * DIM + sub * 4];
        asm volatile("red.global.add.v4.f32 [%0], {%1,%2,%3,%4};"
                     :: "l"(dst), "f"(wn * xs.x), "f"(wn * xs.y),
                        "f"(wn * xs.z), "f"(wn * xs.w)
                     : "memory");
    }
}

// ---------------- bf16-split MMA node kernel ---------------------------------------
// 128 nodes/block, 512 threads (16 warps). Warp = (rg 0..7) x (nh 0..1):
// rows [16rg,16rg+16), n-half nh. Epilogue straight from C fragments.
#define NT 128
#define NTH 512
// smem (u32): W1T(2 planes) | W2T(2 planes) | A/H(2 planes) | b1 | b2
#define SW1 0
#define SW2 (SW1 + 2 * HID * PADW)     // +17408
#define SAH (SW2 + 2 * DIM * PADW)     // +8704
#define SB1 (SAH + 2 * NT * PADW)      // +17408
#define SB2 (SB1 + HID)
#define SMEM_U32 (SB2 + DIM)
#define SMEM_BYTES (SMEM_U32 * 4)      // 174848 B

__global__ void __launch_bounds__(NTH, 1) node_kernel(const float* __restrict__ b1,
                                                      const float* __restrict__ b2) {
    extern __shared__ uint32_t smu[];
    uint32_t* sW1 = smu + SW1;     // hi plane; lo at +HID*PADW
    uint32_t* sW2 = smu + SW2;     // hi; lo at +DIM*PADW
    uint32_t* sAH = smu + SAH;     // hi; lo at +NT*PADW
    float* sB1 = (float*)(smu + SB1);
    float* sB2 = (float*)(smu + SB2);

    int tid = threadIdx.x;
    int base = blockIdx.x * NT;

    // ---- stage weights (straight uint4 copies; layouts identical) ----
    {
        const uint4* s = (const uint4*)g_w1t;
        uint4* d = (uint4*)sW1;
        for (int i = tid; i < (2 * HID * PADW) / 4; i += NTH) d[i] = s[i];
        const uint4* s2 = (const uint4*)g_w2t;
        uint4* d2 = (uint4*)sW2;
        for (int i = tid; i < (2 * DIM * PADW) / 4; i += NTH) d2[i] = s2[i];
    }
    if (tid < HID) sB1[tid] = b1[tid];
    if (tid >= HID && tid < HID + DIM) sB2[tid - HID] = b2[tid - HID];

    // ---- stage A = [x | msg], split to bf16 hi/lo packed pairs ----
    for (int p = tid; p < NT * (HID / 2); p += NTH) {
        int r = p >> 6, cp = p & 63;
        int c = 2 * cp;
        int node = base + r;
        float v0 = 0.f, v1 = 0.f;
        if (node < N_NODES) {
            if (c < DIM) {
                v0 = g_x[node * DIM + c];
                v1 = g_x[node * DIM + c + 1];
            } else {
                v0 = g_msg[node * DIM + c - DIM];
                v1 = g_msg[node * DIM + c - DIM + 1];
            }
        }
        __nv_bfloat16 h0, l0, h1, l1;
        split2(v0, h0, l0);
        split2(v1, h1, l1);
        sAH[r * PADW + cp] = pack2(h0, h1);
        sAH[NT * PADW + r * PADW + cp] = pack2(l0, l1);
    }
    __syncthreads();

    int wid = tid >> 5;
    int lane = tid & 31;
    int rg = wid & 7;        // row group: rows [16rg, 16rg+16)
    int nh = wid >> 3;       // n half
    int grp = lane >> 2;     // 0..7
    int qt = lane & 3;       // 0..3
    int r0 = 16 * rg + grp;  // fragment row (and r0+8)

    // =================== layer 1: H = relu(A @ W1 + b1) ===================
    float c1[8][4];
#pragma unroll
    for (int nt = 0; nt < 8; nt++) {
        int col0 = 64 * nh + 8 * nt + 2 * qt;
        c1[nt][0] = sB1[col0];
        c1[nt][1] = sB1[col0 + 1];
        c1[nt][2] = c1[nt][0];
        c1[nt][3] = c1[nt][1];
    }
#pragma unroll
    for (int kk = 0; kk < 8; kk++) {
        int wc0 = 8 * kk + qt;
        int wc1 = wc0 + 4;
        uint32_t ah0 = sAH[r0 * PADW + wc0];
        uint32_t ah1 = sAH[(r0 + 8) * PADW + wc0];
        uint32_t ah2 = sAH[r0 * PADW + wc1];
        uint32_t ah3 = sAH[(r0 + 8) * PADW + wc1];
        uint32_t al0 = sAH[NT * PADW + r0 * PADW + wc0];
        uint32_t al1 = sAH[NT * PADW + (r0 + 8) * PADW + wc0];
        uint32_t al2 = sAH[NT * PADW + r0 * PADW + wc1];
        uint32_t al3 = sAH[NT * PADW + (r0 + 8) * PADW + wc1];
#pragma unroll
        for (int nt = 0; nt < 8; nt++) {
            int n = 64 * nh + 8 * nt + grp;
            uint32_t bh0 = sW1[n * PADW + wc0];
            uint32_t bh1 = sW1[n * PADW + wc1];
            uint32_t bl0 = sW1[HID * PADW + n * PADW + wc0];
            uint32_t bl1 = sW1[HID * PADW + n * PADW + wc1];
            mma_bf16(c1[nt], ah0, ah1, ah2, ah3, bh0, bh1);
            mma_bf16(c1[nt], ah0, ah1, ah2, ah3, bl0, bl1);
            mma_bf16(c1[nt], al0, al1, al2, al3, bh0, bh1);
        }
    }
    __syncthreads();  // all A reads done before H overwrites the region

    // relu + split + pack -> H (overwrites A planes)
#pragma unroll
    for (int nt = 0; nt < 8; nt++) {
        int wcol = 32 * nh + 4 * nt + qt;     // packed col pair
        float f0 = fmaxf(c1[nt][0], 0.f), f1 = fmaxf(c1[nt][1], 0.f);
        float f2 = fmaxf(c1[nt][2], 0.f), f3 = fmaxf(c1[nt][3], 0.f);
        __nv_bfloat16 h0, l0, h1, l1, h2, l2, h3, l3;
        split2(f0, h0, l0); split2(f1, h1, l1);
        split2(f2, h2, l2); split2(f3, h3, l3);
        sAH[r0 * PADW + wcol] = pack2(h0, h1);
        sAH[NT * PADW + r0 * PADW + wcol] = pack2(l0, l1);
        sAH[(r0 + 8) * PADW + wcol] = pack2(h2, h3);
        sAH[NT * PADW + (r0 + 8) * PADW + wcol] = pack2(l2, l3);
    }
    __syncthreads();

    // =================== layer 2: F = H @ W2 + b2 (N=64) ===================
    float c2[4][4];
#pragma unroll
    for (int nt = 0; nt < 4; nt++) {
        int col0 = 32 * nh + 8 * nt + 2 * qt;
        c2[nt][0] = sB2[col0];
        c2[nt][1] = sB2[col0 + 1];
        c2[nt][2] = c2[nt][0];
        c2[nt][3] = c2[nt][1];
    }
#pragma unroll
    for (int kk = 0; kk < 8; kk++) {
        int wc0 = 8 * kk + qt;
        int wc1 = wc0 + 4;
        uint32_t ah0 = sAH[r0 * PADW + wc0];
        uint32_t ah1 = sAH[(r0 + 8) * PADW + wc0];
        uint32_t ah2 = sAH[r0 * PADW + wc1];
        uint32_t ah3 = sAH[(r0 + 8) * PADW + wc1];
        uint32_t al0 = sAH[NT * PADW + r0 * PADW + wc0];
        uint32_t al1 = sAH[NT * PADW + (r0 + 8) * PADW + wc0];
        uint32_t al2 = sAH[NT * PADW + r0 * PADW + wc1];
        uint32_t al3 = sAH[NT * PADW + (r0 + 8) * PADW + wc1];
#pragma unroll
        for (int nt = 0; nt < 4; nt++) {
            int n = 32 * nh + 8 * nt + grp;
            uint32_t bh0 = sW2[n * PADW + wc0];
            uint32_t bh1 = sW2[n * PADW + wc1];
            uint32_t bl0 = sW2[DIM * PADW + n * PADW + wc0];
            uint32_t bl1 = sW2[DIM * PADW + n * PADW + wc1];
            mma_bf16(c2[nt], ah0, ah1, ah2, ah3, bh0, bh1);
            mma_bf16(c2[nt], ah0, ah1, ah2, ah3, bl0, bl1);
            mma_bf16(c2[nt], al0, al1, al2, al3, bh0, bh1);
        }
    }

    // ---- epilogue straight from fragments: x += DT*(f-x); e update; msg=0 ----
#pragma unroll
    for (int nt = 0; nt < 4; nt++) {
        int col0 = 32 * nh + 8 * nt + 2 * qt;
#pragma unroll
        for (int half = 0; half < 2; half++) {
            int node = base + r0 + 8 * half;
            if (node < N_NODES) {
                int gi = node * DIM + col0;
                float f0 = c2[nt][2 * half];
                float f1 = c2[nt][2 * half + 1];
                float2 xv = *(float2*)&g_x[gi];
                float2 xn = make_float2(xv.x + DT * (f0 - xv.x),
                                        xv.y + DT * (f1 - xv.y));
                *(float2*)&g_x[gi] = xn;
                float2 ev = *(float2*)&g_e[gi];
                ev.x = ev.x + DT * (xn.x - ev.x * (1.0f / TAU));
                ev.y = ev.y + DT * (xn.y - ev.y * (1.0f / TAU));
                *(float2*)&g_e[gi] = ev;
                *(float2*)&g_msg[gi] = make_float2(0.f, 0.f);
            }
        }
    }
}

// ---------------- output: [x (3.2M) | w (0.8M)] -----------------------------------
__global__ void finalize_kernel(float* __restrict__ out) {
    int i = blockIdx.x * blockDim.x + threadIdx.x;
    if (i < N_NODES * DIM) out[i] = g_x[i];
    else if (i < N_NODES * DIM + N_EDGES) out[i] = g_w[i - N_NODES * DIM];
}

// ---------------- launch ------------------------------------------------------------
extern "C" void kernel_launch(void* const* d_in, const int* in_sizes, int n_in,
                              void* d_out, int out_size) {
    const float* x_in  = (const float*)d_in[0];
    const void*  ei    = d_in[1];
    const float* ea    = (const float*)d_in[2];
    const float* etap  = (const float*)d_in[3];
    const float* etam  = (const float*)d_in[4];
    const float* W1    = (const float*)d_in[5];
    const float* b1    = (const float*)d_in[6];
    const float* W2    = (const float*)d_in[7];
    const float* b2    = (const float*)d_in[8];

    cudaFuncSetAttribute(node_kernel, cudaFuncAttributeMaxDynamicSharedMemorySize,
                         SMEM_BYTES);

    const int EBLK = (N_EDGES * 16) / 256;            // 50000
    const int NBLK = (N_NODES + NT - 1) / NT;         // 391
    const int PREP = HID * (HID / 2) + DIM * (HID / 2);

    convert_init_kernel<<<(N_NODES * DIM + 255) / 256, 256>>>(ei, ea, x_in);
    prep_weights_kernel<<<(PREP + 255) / 256, 256>>>(W1, W2);
    edge_kernel<false, true><<<EBLK, 256>>>(etap, etam);
    // launch 3 (ncu-profiled slot): node kernel
    node_kernel<<<NBLK, NTH, SMEM_BYTES>>>(b1, b2);

    for (int t = 1; t < N_STEPS; t++) {
        edge_kernel<true, true><<<EBLK, 256>>>(etap, etam);
        node_kernel<<<NBLK, NTH, SMEM_BYTES>>>(b1, b2);
    }
    edge_kernel<true, false><<<EBLK, 256>>>(etap, etam);

    finalize_kernel<<<(N_NODES * DIM + N_EDGES + 255) / 256, 256>>>((float*)d_out);
}